// round 13
// baseline (speedup 1.0000x reference)
#include <cuda_runtime.h>
#include <cuda_bf16.h>

#define BB 256      // batch
#define MM 8        // metapaths
#define LL 64       // walk length
#define EE 128      // embedding
#define HH 8        // heads
#define HD 16       // head dim
#define JQKV 384    // 3*E

// Scratch (no cudaMalloc allowed)
__device__ float g_agg0[BB * MM * EE];          // [(b*8+m)][e]
__device__ float g_agg1[BB * MM * EE];          // [(b*8+m)][e]

// packed f32x2 FMA
__device__ __forceinline__ unsigned long long ffma2(unsigned long long a,
                                                    unsigned long long b,
                                                    unsigned long long c) {
    unsigned long long d;
    asm("fma.rn.f32x2 %0, %1, %2, %3;" : "=l"(d) : "l"(a), "l"(b), "l"(c));
    return d;
}
__device__ __forceinline__ unsigned long long pack2(float lo, float hi) {
    unsigned long long d;
    asm("mov.b64 %0, {%1, %2};" : "=l"(d) : "f"(lo), "f"(hi));
    return d;
}
__device__ __forceinline__ void unpack2(unsigned long long v, float& lo, float& hi) {
    asm("mov.b64 {%0, %1}, %2;" : "=f"(lo), "=f"(hi) : "l"(v));
}

// ---------------------------------------------------------------------------
// K1: gather + fuse + mean.  1 walk per block, 128 thr = 4 warps x 16 steps.
// grid = 2048 blocks.  FULL unroll -> ~32 outstanding LDG.128 per warp.
// ---------------------------------------------------------------------------
__global__ __launch_bounds__(128) void k_gather(
    const int* __restrict__ walks,        // [B,M,L,3]
    const float* __restrict__ nt,         // [NUM_NODES, E]
    const float* __restrict__ fb,         // [E]
    const float* __restrict__ et)         // [8, E]
{
    __shared__ int sw[LL * 3];
    __shared__ __align__(16) float se[8 * EE];
    __shared__ __align__(16) float s_red[4 * EE];
    const int t    = threadIdx.x;
    const int lane = t & 31;
    const int w    = t >> 5;              // warp = L-segment 0..3
    const int bm   = blockIdx.x;

    for (int i = t; i < LL * 3; i += 128) sw[i] = walks[bm * (LL * 3) + i];
    for (int i = t; i < 8 * EE; i += 128) se[i] = et[i];
    const float4  fb4 = ((const float4*)fb)[lane];
    const float4* nt4 = (const float4*)nt;
    const float4* se4 = (const float4*)se;
    __syncthreads();

    const int* swp = &sw[w * 48];         // 16 steps * 3

    // front-batch all 32 global loads
    float4 av[16], bv[16];
#pragma unroll
    for (int l = 0; l < 16; ++l) {
        av[l] = nt4[swp[3 * l + 0] * 32 + lane];
        bv[l] = nt4[swp[3 * l + 1] * 32 + lane];
    }

    float4 acc = make_float4(0.f, 0.f, 0.f, 0.f);
#pragma unroll
    for (int l = 0; l < 16; ++l) {
        const float4 e = se4[swp[3 * l + 2] * 32 + lane];
        acc.x += (av[l].x + fb4.x) * (bv[l].x + fb4.x) * e.x;
        acc.y += (av[l].y + fb4.y) * (bv[l].y + fb4.y) * e.y;
        acc.z += (av[l].z + fb4.z) * (bv[l].z + fb4.z) * e.z;
        acc.w += (av[l].w + fb4.w) * (bv[l].w + fb4.w) * e.w;
    }
    ((float4*)s_red)[w * 32 + lane] = acc;
    __syncthreads();

    const float s = (s_red[0 * EE + t] + s_red[1 * EE + t] +
                     s_red[2 * EE + t] + s_red[3 * EE + t]) * (1.0f / (float)LL);
    g_agg0[bm * EE + t] = s;
}

// ---------------------------------------------------------------------------
// K2: per-metapath linear, 8 rows/block, e-dim split over 2 thread halves.
// grid = (B/8, M) = 256 blocks, 256 thr.
// ---------------------------------------------------------------------------
__global__ __launch_bounds__(256) void k_mp(
    const int* __restrict__ mpidx,
    const float* __restrict__ W,          // [M,E,E] ('meo': W[m][e][o])
    const float* __restrict__ bmp)        // [M,E]
{
    __shared__ __align__(16) float At[EE * 8];      // [e][r]
    __shared__ __align__(16) float s_red[2 * 1024]; // [h][o*8+r]
    const int t  = threadIdx.x;
    const int o  = t & 127;
    const int h  = t >> 7;                // e-half
    const int b0 = blockIdx.x * 8;
    const int m  = blockIdx.y;
    const int wm = mpidx[m];

    for (int i = t; i < 8 * EE; i += 256) {
        const int r = i >> 7, e = i & 127;
        At[e * 8 + r] = g_agg0[((b0 + r) * MM + m) * EE + e];
    }
    __syncthreads();

    unsigned long long acc2[4];
#pragma unroll
    for (int k = 0; k < 4; ++k) acc2[k] = 0ULL;

    const float* Wm = W + wm * EE * EE + (h * 64) * EE;
    const float* Ab = &At[(h * 64) * 8];
#pragma unroll 8
    for (int e = 0; e < 64; ++e) {
        const float w = Wm[e * EE + o];
        const unsigned long long ww = pack2(w, w);
        const ulonglong2* ap = (const ulonglong2*)&Ab[e * 8];
        ulonglong2 a0 = ap[0];
        ulonglong2 a1 = ap[1];
        acc2[0] = ffma2(a0.x, ww, acc2[0]);
        acc2[1] = ffma2(a0.y, ww, acc2[1]);
        acc2[2] = ffma2(a1.x, ww, acc2[2]);
        acc2[3] = ffma2(a1.y, ww, acc2[3]);
    }
#pragma unroll
    for (int k = 0; k < 4; ++k) {
        float lo, hi;
        unpack2(acc2[k], lo, hi);
        s_red[h * 1024 + o * 8 + 2 * k + 0] = lo;
        s_red[h * 1024 + o * 8 + 2 * k + 1] = hi;
    }
    __syncthreads();

    const float bias = bmp[wm * EE + o];
#pragma unroll
    for (int k = 0; k < 4; ++k) {
        const int r = k * 2 + h;          // rows 0..7, coalesced in o
        const float v = s_red[0 * 1024 + o * 8 + r] +
                        s_red[1 * 1024 + o * 8 + r] + bias;
        g_agg1[((b0 + r) * MM + m) * EE + o] = v;
    }
}

// ---------------------------------------------------------------------------
// K3: fused QKV + attention + output projection.
// grid = 128 blocks, 256 thr, 2 batches/block.  Dynamic smem = 100 KB:
//   s_ws  [0,16384)      full 128x128 weight chunk (swizzled)
//   s_ao  [16384,18432)  agg1 staged / attn-out, [g][e*8+m]
//   s_qkv [18432,24576)  [g][m][384]
//   s_att [24576,25600)  attention probs (separate -> Wo prefetch overlap)
// ---------------------------------------------------------------------------
__global__ __launch_bounds__(256) void k_mha(
    const float* __restrict__ Wq,         // [384,128]
    const float* __restrict__ bq,         // [384]
    const float* __restrict__ Wo,         // [128,128]
    const float* __restrict__ bo,         // [128]
    float* __restrict__ out)              // [M,B,E]
{
    extern __shared__ __align__(16) float smem[];
    float* s_ws  = smem;                  // 16384
    float* s_ao  = smem + 16384;          // 2048
    float* s_qkv = smem + 18432;          // 6144
    float* s_att = smem + 24576;          // 1024

    const int t  = threadIdx.x;
    const int g  = t >> 7;                // batch-local 0/1
    const int j  = t & 127;
    const int b0 = blockIdx.x * 2;

    // ---- Stage A: agg1 transposed into s_ao + first Wq chunk into s_ws ----
    for (int i = t; i < 2048; i += 256) {
        const int r = i >> 7;             // gg*8+m
        const int e = i & 127;
        const int gg = r >> 3, mm = r & 7;
        s_ao[gg * 1024 + e * 8 + mm] = g_agg1[((b0 + gg) * MM + mm) * EE + e];
    }
    for (int i = t; i < 16384; i += 256) {
        const int jj = i >> 7, ee = i & 127;
        s_ws[jj * 128 + (ee ^ (jj & 31))] = Wq[jj * EE + ee];
    }

    // ---- Stage B: QKV, one full 128x128 weight chunk per jc ----
    for (int jc = 0; jc < 3; ++jc) {
        const int j0 = jc * 128;
        if (jc > 0) {
            __syncthreads();              // protect prev s_ws readers
            for (int i = t; i < 16384; i += 256) {
                const int jj = i >> 7, ee = i & 127;
                s_ws[jj * 128 + (ee ^ (jj & 31))] = Wq[(j0 + jj) * EE + ee];
            }
        }
        __syncthreads();

        unsigned long long acc2[4];
#pragma unroll
        for (int k = 0; k < 4; ++k) acc2[k] = 0ULL;
#pragma unroll 8
        for (int e = 0; e < 128; ++e) {
            const float w = s_ws[j * 128 + (e ^ (j & 31))];
            const unsigned long long ww = pack2(w, w);
            const ulonglong2* ap = (const ulonglong2*)&s_ao[g * 1024 + e * 8];
            ulonglong2 a0 = ap[0];
            ulonglong2 a1 = ap[1];
            acc2[0] = ffma2(a0.x, ww, acc2[0]);
            acc2[1] = ffma2(a0.y, ww, acc2[1]);
            acc2[2] = ffma2(a1.x, ww, acc2[2]);
            acc2[3] = ffma2(a1.y, ww, acc2[3]);
        }
        const float bias = bq[j0 + j];
#pragma unroll
        for (int k = 0; k < 4; ++k) {
            float lo, hi;
            unpack2(acc2[k], lo, hi);
            s_qkv[g * 3072 + (2 * k + 0) * JQKV + j0 + j] = lo + bias;
            s_qkv[g * 3072 + (2 * k + 1) * JQKV + j0 + j] = hi + bias;
        }
    }
    __syncthreads();                      // qkv complete; s_ws dead

    // ---- Stage C: softmax (warps 0-3) || Wo prefetch (warps 4-7) ----
    if (t < 128) {
        const int gg = t >> 6;
        const int hm = t & 63;
        const int h  = hm >> 3;
        const int m  = hm & 7;
        const float* qp = &s_qkv[gg * 3072 + m * JQKV + h * HD];
        float sc[MM];
#pragma unroll
        for (int n = 0; n < MM; ++n) {
            const float* kp = &s_qkv[gg * 3072 + n * JQKV + EE + h * HD];
            float s = 0.0f;
#pragma unroll
            for (int d = 0; d < HD; ++d) s += qp[d] * kp[d];
            sc[n] = s * 0.25f;            // 1/sqrt(16)
        }
        float mx = sc[0];
#pragma unroll
        for (int n = 1; n < MM; ++n) mx = fmaxf(mx, sc[n]);
        float sum = 0.0f;
#pragma unroll
        for (int n = 0; n < MM; ++n) { sc[n] = __expf(sc[n] - mx); sum += sc[n]; }
        const float inv = 1.0f / sum;
#pragma unroll
        for (int n = 0; n < MM; ++n)
            s_att[(gg * 64 + hm) * 8 + n] = sc[n] * inv;
    } else {
        const int tt = t - 128;           // 128 threads stage all of Wo
        for (int i = tt; i < 16384; i += 128) {
            const int jj = i >> 7, ee = i & 127;
            s_ws[jj * 128 + (ee ^ (jj & 31))] = Wo[jj * EE + ee];
        }
    }
    __syncthreads();

    {   // AV: o[g][e][m], e = j
        const int h = j >> 4;
        const float* vp = &s_qkv[g * 3072 + 2 * EE + j];
        float ov[MM];
#pragma unroll
        for (int m = 0; m < MM; ++m) {
            float v = 0.0f;
            const float* ap = &s_att[(g * 64 + h * 8 + m) * 8];
#pragma unroll
            for (int n = 0; n < MM; ++n) v += ap[n] * vp[n * JQKV];
            ov[m] = v;
        }
        __syncthreads();                  // done reading s_ao (stage B) & s_att
#pragma unroll
        for (int m = 0; m < MM; ++m)
            s_ao[g * 1024 + j * 8 + m] = ov[m];
    }
    __syncthreads();                      // s_ao attn-out + s_ws Wo ready

    // ---- Stage D: output projection (Wo already staged) ----
    {
        unsigned long long acc2[4];
#pragma unroll
        for (int k = 0; k < 4; ++k) acc2[k] = 0ULL;
#pragma unroll 8
        for (int e = 0; e < 128; ++e) {
            const float w = s_ws[j * 128 + (e ^ (j & 31))];
            const unsigned long long ww = pack2(w, w);
            const ulonglong2* ap = (const ulonglong2*)&s_ao[g * 1024 + e * 8];
            ulonglong2 a0 = ap[0];
            ulonglong2 a1 = ap[1];
            acc2[0] = ffma2(a0.x, ww, acc2[0]);
            acc2[1] = ffma2(a0.y, ww, acc2[1]);
            acc2[2] = ffma2(a1.x, ww, acc2[2]);
            acc2[3] = ffma2(a1.y, ww, acc2[3]);
        }
        const float bias = bo[j];
        const int b = b0 + g;
#pragma unroll
        for (int k = 0; k < 4; ++k) {
            float lo, hi;
            unpack2(acc2[k], lo, hi);
            out[((2 * k + 0) * BB + b) * EE + j] = lo + bias;
            out[((2 * k + 1) * BB + b) * EE + j] = hi + bias;
        }
    }
}

// ---------------------------------------------------------------------------
extern "C" void kernel_launch(void* const* d_in, const int* in_sizes, int n_in,
                              void* d_out, int out_size) {
    const int*   mp_type = (const int*)d_in[1];
    const int*   walks   = (const int*)d_in[2];
    const float* nt      = (const float*)d_in[3];
    const float* fb      = (const float*)d_in[4];
    const float* et      = (const float*)d_in[5];
    const float* W_mp    = (const float*)d_in[6];
    const float* b_mp    = (const float*)d_in[7];
    const float* Wqkv    = (const float*)d_in[8];
    const float* bqkv    = (const float*)d_in[9];
    const float* Wo      = (const float*)d_in[10];
    const float* bo      = (const float*)d_in[11];
    float* out = (float*)d_out;

    static const size_t MHA_SMEM = 25600 * sizeof(float);   // 100 KB
    cudaFuncSetAttribute(k_mha, cudaFuncAttributeMaxDynamicSharedMemorySize,
                         (int)MHA_SMEM);

    k_gather<<<BB * MM, 128>>>(walks, nt, fb, et);
    k_mp<<<dim3(BB / 8, MM), 256>>>(mp_type, W_mp, b_mp);
    k_mha<<<BB / 2, 256, MHA_SMEM>>>(Wqkv, bqkv, Wo, bo, out);
}

// round 14
// speedup vs baseline: 1.0864x; 1.0864x over previous
#include <cuda_runtime.h>
#include <cuda_bf16.h>

#define BB 256      // batch
#define MM 8        // metapaths
#define LL 64       // walk length
#define EE 128      // embedding
#define HH 8        // heads
#define HD 16       // head dim
#define JQKV 384    // 3*E

// Scratch (no cudaMalloc allowed)
__device__ float g_agg0[BB * MM * EE];          // [(b*8+m)][e]
__device__ float g_agg1[BB * MM * EE];          // [(b*8+m)][e]

// packed f32x2 FMA
__device__ __forceinline__ unsigned long long ffma2(unsigned long long a,
                                                    unsigned long long b,
                                                    unsigned long long c) {
    unsigned long long d;
    asm("fma.rn.f32x2 %0, %1, %2, %3;" : "=l"(d) : "l"(a), "l"(b), "l"(c));
    return d;
}
__device__ __forceinline__ unsigned long long pack2(float lo, float hi) {
    unsigned long long d;
    asm("mov.b64 %0, {%1, %2};" : "=l"(d) : "f"(lo), "f"(hi));
    return d;
}
__device__ __forceinline__ void unpack2(unsigned long long v, float& lo, float& hi) {
    asm("mov.b64 {%0, %1}, %2;" : "=f"(lo), "=f"(hi) : "l"(v));
}

// ---------------------------------------------------------------------------
// K1: gather + fuse + mean (ROUND-10 SHAPE: unroll 4, 32 regs, high occ).
// 1 walk per block, 128 thr = 4 warps x 16 steps.  grid = 2048.
// ---------------------------------------------------------------------------
__global__ __launch_bounds__(128) void k_gather(
    const int* __restrict__ walks,        // [B,M,L,3]
    const float* __restrict__ nt,         // [NUM_NODES, E]
    const float* __restrict__ fb,         // [E]
    const float* __restrict__ et)         // [8, E]
{
    __shared__ int sw[LL * 3];
    __shared__ __align__(16) float se[8 * EE];
    __shared__ __align__(16) float s_red[4 * EE];
    const int t    = threadIdx.x;
    const int lane = t & 31;
    const int w    = t >> 5;              // warp = L-segment 0..3
    const int bm   = blockIdx.x;

    for (int i = t; i < LL * 3; i += 128) sw[i] = walks[bm * (LL * 3) + i];
    for (int i = t; i < 8 * EE; i += 128) se[i] = et[i];
    const float4  fb4 = ((const float4*)fb)[lane];
    const float4* nt4 = (const float4*)nt;
    const float4* se4 = (const float4*)se;
    __syncthreads();

    float4 acc = make_float4(0.f, 0.f, 0.f, 0.f);
    const int* swp = &sw[w * 48];         // 16 steps * 3
#pragma unroll 4
    for (int l = 0; l < 16; ++l) {
        const int n1 = swp[3 * l + 0];
        const int n2 = swp[3 * l + 1];
        const int ey = swp[3 * l + 2];
        float4 a = nt4[n1 * 32 + lane];
        float4 b = nt4[n2 * 32 + lane];
        float4 e = se4[ey * 32 + lane];
        acc.x += (a.x + fb4.x) * (b.x + fb4.x) * e.x;
        acc.y += (a.y + fb4.y) * (b.y + fb4.y) * e.y;
        acc.z += (a.z + fb4.z) * (b.z + fb4.z) * e.z;
        acc.w += (a.w + fb4.w) * (b.w + fb4.w) * e.w;
    }
    ((float4*)s_red)[w * 32 + lane] = acc;
    __syncthreads();

    const float s = (s_red[0 * EE + t] + s_red[1 * EE + t] +
                     s_red[2 * EE + t] + s_red[3 * EE + t]) * (1.0f / (float)LL);
    g_agg0[bm * EE + t] = s;
}

// ---------------------------------------------------------------------------
// K2: per-metapath linear, 8 rows/block, e-dim split over 2 thread halves.
// grid = (B/8, M) = 256 blocks, 256 thr.
// ---------------------------------------------------------------------------
__global__ __launch_bounds__(256) void k_mp(
    const int* __restrict__ mpidx,
    const float* __restrict__ W,          // [M,E,E] ('meo': W[m][e][o])
    const float* __restrict__ bmp)        // [M,E]
{
    __shared__ __align__(16) float At[EE * 8];      // [e][r]
    __shared__ __align__(16) float s_red[2 * 1024]; // [h][o*8+r]
    const int t  = threadIdx.x;
    const int o  = t & 127;
    const int h  = t >> 7;                // e-half
    const int b0 = blockIdx.x * 8;
    const int m  = blockIdx.y;
    const int wm = mpidx[m];

    for (int i = t; i < 8 * EE; i += 256) {
        const int r = i >> 7, e = i & 127;
        At[e * 8 + r] = g_agg0[((b0 + r) * MM + m) * EE + e];
    }
    __syncthreads();

    unsigned long long acc2[4];
#pragma unroll
    for (int k = 0; k < 4; ++k) acc2[k] = 0ULL;

    const float* Wm = W + wm * EE * EE + (h * 64) * EE;
    const float* Ab = &At[(h * 64) * 8];
#pragma unroll 8
    for (int e = 0; e < 64; ++e) {
        const float w = Wm[e * EE + o];
        const unsigned long long ww = pack2(w, w);
        const ulonglong2* ap = (const ulonglong2*)&Ab[e * 8];
        ulonglong2 a0 = ap[0];
        ulonglong2 a1 = ap[1];
        acc2[0] = ffma2(a0.x, ww, acc2[0]);
        acc2[1] = ffma2(a0.y, ww, acc2[1]);
        acc2[2] = ffma2(a1.x, ww, acc2[2]);
        acc2[3] = ffma2(a1.y, ww, acc2[3]);
    }
#pragma unroll
    for (int k = 0; k < 4; ++k) {
        float lo, hi;
        unpack2(acc2[k], lo, hi);
        s_red[h * 1024 + o * 8 + 2 * k + 0] = lo;
        s_red[h * 1024 + o * 8 + 2 * k + 1] = hi;
    }
    __syncthreads();

    const float bias = bmp[wm * EE + o];
#pragma unroll
    for (int k = 0; k < 4; ++k) {
        const int r = k * 2 + h;          // rows 0..7, coalesced in o
        const float v = s_red[0 * 1024 + o * 8 + r] +
                        s_red[1 * 1024 + o * 8 + r] + bias;
        g_agg1[((b0 + r) * MM + m) * EE + o] = v;
    }
}

// ---------------------------------------------------------------------------
// K3: fused QKV + attention + output projection, 1 BATCH PER BLOCK.
// grid = 256 blocks, 256 thr.  Thread = (j = t&127, half = t>>7):
// half owns metapaths m in [half*4, half*4+4).  Dynamic smem 84 KB:
//   s_ws  [0,16384)      128x128 weight chunk (swizzled)
//   s_ao  [16384,17408)  agg1 staged / attn-out, [e*8+m]
//   s_qkv [17408,20480)  [m][384]
//   s_att [20480,20992)  [h][m][n]
// ---------------------------------------------------------------------------
__global__ __launch_bounds__(256) void k_mha(
    const float* __restrict__ Wq,         // [384,128]
    const float* __restrict__ bq,         // [384]
    const float* __restrict__ Wo,         // [128,128]
    const float* __restrict__ bo,         // [128]
    float* __restrict__ out)              // [M,B,E]
{
    extern __shared__ __align__(16) float smem[];
    float* s_ws  = smem;                  // 16384
    float* s_ao  = smem + 16384;          // 1024
    float* s_qkv = smem + 17408;          // 3072
    float* s_att = smem + 20480;          // 512

    const int t    = threadIdx.x;
    const int j    = t & 127;
    const int half = t >> 7;              // m-group 0/1
    const int b    = blockIdx.x;

    // ---- Stage A: agg1 transposed into s_ao + first Wq chunk ----
    for (int i = t; i < 1024; i += 256) {
        const int mm = i >> 7;            // m
        const int e  = i & 127;
        s_ao[e * 8 + mm] = g_agg1[(b * MM + mm) * EE + e];
    }
    for (int i = t; i < 16384; i += 256) {
        const int jj = i >> 7, ee = i & 127;
        s_ws[jj * 128 + (ee ^ (jj & 31))] = Wq[jj * EE + ee];
    }

    // ---- Stage B: QKV, one full 128x128 weight chunk per jc ----
    for (int jc = 0; jc < 3; ++jc) {
        const int j0 = jc * 128;
        if (jc > 0) {
            __syncthreads();              // prev s_ws readers done
            for (int i = t; i < 16384; i += 256) {
                const int jj = i >> 7, ee = i & 127;
                s_ws[jj * 128 + (ee ^ (jj & 31))] = Wq[(j0 + jj) * EE + ee];
            }
        }
        __syncthreads();

        unsigned long long acc2[2] = {0ULL, 0ULL};
#pragma unroll 8
        for (int e = 0; e < 128; ++e) {
            const float w = s_ws[j * 128 + (e ^ (j & 31))];
            const unsigned long long ww = pack2(w, w);
            const ulonglong2 a = *(const ulonglong2*)&s_ao[e * 8 + half * 4];
            acc2[0] = ffma2(a.x, ww, acc2[0]);
            acc2[1] = ffma2(a.y, ww, acc2[1]);
        }
        const float bias = bq[j0 + j];
#pragma unroll
        for (int k = 0; k < 2; ++k) {
            float lo, hi;
            unpack2(acc2[k], lo, hi);
            s_qkv[(half * 4 + 2 * k + 0) * JQKV + j0 + j] = lo + bias;
            s_qkv[(half * 4 + 2 * k + 1) * JQKV + j0 + j] = hi + bias;
        }
    }
    __syncthreads();                      // qkv complete; s_ws dead

    // ---- Stage C: softmax (t<64) || Wo prefetch (t>=128) ----
    if (t < 64) {
        const int h = t >> 3;
        const int m = t & 7;
        const float* qp = &s_qkv[m * JQKV + h * HD];
        float sc[MM];
#pragma unroll
        for (int n = 0; n < MM; ++n) {
            const float* kp = &s_qkv[n * JQKV + EE + h * HD];
            float s = 0.0f;
#pragma unroll
            for (int d = 0; d < HD; ++d) s += qp[d] * kp[d];
            sc[n] = s * 0.25f;            // 1/sqrt(16)
        }
        float mx = sc[0];
#pragma unroll
        for (int n = 1; n < MM; ++n) mx = fmaxf(mx, sc[n]);
        float sum = 0.0f;
#pragma unroll
        for (int n = 0; n < MM; ++n) { sc[n] = __expf(sc[n] - mx); sum += sc[n]; }
        const float inv = 1.0f / sum;
#pragma unroll
        for (int n = 0; n < MM; ++n)
            s_att[(h * MM + (t & 7)) * MM + n] = sc[n] * inv;
    } else if (t >= 128) {
        const int tt = t - 128;           // 128 threads stage all of Wo
        for (int i = tt; i < 16384; i += 128) {
            const int jj = i >> 7, ee = i & 127;
            s_ws[jj * 128 + (ee ^ (jj & 31))] = Wo[jj * EE + ee];
        }
    }
    __syncthreads();

    {   // AV: o[e=j][m] for this thread's 4 m's
        const int h = j >> 4;
        const float* vp = &s_qkv[2 * EE + j];
        float ov[4];
#pragma unroll
        for (int k = 0; k < 4; ++k) {
            const int m = half * 4 + k;
            float v = 0.0f;
            const float* ap = &s_att[(h * MM + m) * MM];
#pragma unroll
            for (int n = 0; n < MM; ++n) v += ap[n] * vp[n * JQKV];
            ov[k] = v;
        }
        __syncthreads();                  // s_ao (stage B operand) dead
#pragma unroll
        for (int k = 0; k < 4; ++k)
            s_ao[j * 8 + half * 4 + k] = ov[k];
    }
    __syncthreads();                      // attn-out + Wo staged

    // ---- Stage D: output projection (Wo already in s_ws) ----
    {
        unsigned long long acc2[2] = {0ULL, 0ULL};
#pragma unroll 8
        for (int e = 0; e < 128; ++e) {
            const float w = s_ws[j * 128 + (e ^ (j & 31))];
            const unsigned long long ww = pack2(w, w);
            const ulonglong2 a = *(const ulonglong2*)&s_ao[e * 8 + half * 4];
            acc2[0] = ffma2(a.x, ww, acc2[0]);
            acc2[1] = ffma2(a.y, ww, acc2[1]);
        }
        const float bias = bo[j];
#pragma unroll
        for (int k = 0; k < 2; ++k) {
            float lo, hi;
            unpack2(acc2[k], lo, hi);
            const int m0 = half * 4 + 2 * k;
            out[((m0 + 0) * BB + b) * EE + j] = lo + bias;
            out[((m0 + 1) * BB + b) * EE + j] = hi + bias;
        }
    }
}

// ---------------------------------------------------------------------------
extern "C" void kernel_launch(void* const* d_in, const int* in_sizes, int n_in,
                              void* d_out, int out_size) {
    const int*   mp_type = (const int*)d_in[1];
    const int*   walks   = (const int*)d_in[2];
    const float* nt      = (const float*)d_in[3];
    const float* fb      = (const float*)d_in[4];
    const float* et      = (const float*)d_in[5];
    const float* W_mp    = (const float*)d_in[6];
    const float* b_mp    = (const float*)d_in[7];
    const float* Wqkv    = (const float*)d_in[8];
    const float* bqkv    = (const float*)d_in[9];
    const float* Wo      = (const float*)d_in[10];
    const float* bo      = (const float*)d_in[11];
    float* out = (float*)d_out;

    static const size_t MHA_SMEM = 20992 * sizeof(float);   // 84 KB
    cudaFuncSetAttribute(k_mha, cudaFuncAttributeMaxDynamicSharedMemorySize,
                         (int)MHA_SMEM);

    k_gather<<<BB * MM, 128>>>(walks, nt, fb, et);
    k_mp<<<dim3(BB / 8, MM), 256>>>(mp_type, W_mp, b_mp);
    k_mha<<<BB, 256, MHA_SMEM>>>(Wqkv, bqkv, Wo, bo, out);
}

// round 15
// speedup vs baseline: 1.1318x; 1.0418x over previous
#include <cuda_runtime.h>
#include <cuda_bf16.h>

#define BB 256      // batch
#define MM 8        // metapaths
#define LL 64       // walk length
#define EE 128      // embedding
#define HH 8        // heads
#define HD 16       // head dim
#define JQKV 384    // 3*E

// Scratch (no cudaMalloc allowed)
__device__ float g_agg0[BB * MM * EE];          // [(b*8+m)][e]
__device__ float g_agg1[BB * MM * EE];          // [(b*8+m)][e]

// packed f32x2 FMA
__device__ __forceinline__ unsigned long long ffma2(unsigned long long a,
                                                    unsigned long long b,
                                                    unsigned long long c) {
    unsigned long long d;
    asm("fma.rn.f32x2 %0, %1, %2, %3;" : "=l"(d) : "l"(a), "l"(b), "l"(c));
    return d;
}
__device__ __forceinline__ unsigned long long pack2(float lo, float hi) {
    unsigned long long d;
    asm("mov.b64 %0, {%1, %2};" : "=l"(d) : "f"(lo), "f"(hi));
    return d;
}
__device__ __forceinline__ void unpack2(unsigned long long v, float& lo, float& hi) {
    asm("mov.b64 {%0, %1}, %2;" : "=f"(lo), "=f"(hi) : "l"(v));
}

// ---------------------------------------------------------------------------
// K1: gather + fuse + mean (round-10 shape: unroll 4, 32 regs, 79% occ).
// 1 walk per block, 128 thr = 4 warps x 16 steps.  grid = 2048.
// ---------------------------------------------------------------------------
__global__ __launch_bounds__(128) void k_gather(
    const int* __restrict__ walks,        // [B,M,L,3]
    const float* __restrict__ nt,         // [NUM_NODES, E]
    const float* __restrict__ fb,         // [E]
    const float* __restrict__ et)         // [8, E]
{
    __shared__ int sw[LL * 3];
    __shared__ __align__(16) float se[8 * EE];
    __shared__ __align__(16) float s_red[4 * EE];
    const int t    = threadIdx.x;
    const int lane = t & 31;
    const int w    = t >> 5;              // warp = L-segment 0..3
    const int bm   = blockIdx.x;

    for (int i = t; i < LL * 3; i += 128) sw[i] = walks[bm * (LL * 3) + i];
    for (int i = t; i < 8 * EE; i += 128) se[i] = et[i];
    const float4  fb4 = ((const float4*)fb)[lane];
    const float4* nt4 = (const float4*)nt;
    const float4* se4 = (const float4*)se;
    __syncthreads();

    float4 acc = make_float4(0.f, 0.f, 0.f, 0.f);
    const int* swp = &sw[w * 48];         // 16 steps * 3
#pragma unroll 4
    for (int l = 0; l < 16; ++l) {
        const int n1 = swp[3 * l + 0];
        const int n2 = swp[3 * l + 1];
        const int ey = swp[3 * l + 2];
        float4 a = nt4[n1 * 32 + lane];
        float4 b = nt4[n2 * 32 + lane];
        float4 e = se4[ey * 32 + lane];
        acc.x += (a.x + fb4.x) * (b.x + fb4.x) * e.x;
        acc.y += (a.y + fb4.y) * (b.y + fb4.y) * e.y;
        acc.z += (a.z + fb4.z) * (b.z + fb4.z) * e.z;
        acc.w += (a.w + fb4.w) * (b.w + fb4.w) * e.w;
    }
    ((float4*)s_red)[w * 32 + lane] = acc;
    __syncthreads();

    const float s = (s_red[0 * EE + t] + s_red[1 * EE + t] +
                     s_red[2 * EE + t] + s_red[3 * EE + t]) * (1.0f / (float)LL);
    g_agg0[bm * EE + t] = s;
}

// ---------------------------------------------------------------------------
// K2: per-metapath linear, 8 rows/block, e-dim split over 4 thread quarters.
// grid = (B/8, M) = 256 blocks, 512 thr (16 warps -> deep latency hiding).
// ---------------------------------------------------------------------------
__global__ __launch_bounds__(512) void k_mp(
    const int* __restrict__ mpidx,
    const float* __restrict__ W,          // [M,E,E] ('meo': W[m][e][o])
    const float* __restrict__ bmp)        // [M,E]
{
    __shared__ __align__(16) float At[EE * 8];       // [e][r]
    __shared__ __align__(16) float s_red[4 * 1152];  // [h][o*9+r], pad9
    const int t  = threadIdx.x;
    const int o  = t & 127;
    const int h  = t >> 7;                // e-quarter 0..3
    const int b0 = blockIdx.x * 8;
    const int m  = blockIdx.y;
    const int wm = mpidx[m];

    // stage A (8 rows x 128) via float4, transposed to [e][r]
    for (int i = t; i < 256; i += 512) {
        const int r = i >> 5, q = i & 31;
        const float4 v = ((const float4*)g_agg0)[((b0 + r) * MM + m) * 32 + q];
        At[(4 * q + 0) * 8 + r] = v.x;
        At[(4 * q + 1) * 8 + r] = v.y;
        At[(4 * q + 2) * 8 + r] = v.z;
        At[(4 * q + 3) * 8 + r] = v.w;
    }
    __syncthreads();

    unsigned long long acc2[4];
#pragma unroll
    for (int k = 0; k < 4; ++k) acc2[k] = 0ULL;

    const float* Wm = W + wm * EE * EE + (h * 32) * EE;
    const float* Ab = &At[(h * 32) * 8];
#pragma unroll 8
    for (int e = 0; e < 32; ++e) {
        const float w = Wm[e * EE + o];
        const unsigned long long ww = pack2(w, w);
        const ulonglong2* ap = (const ulonglong2*)&Ab[e * 8];
        ulonglong2 a0 = ap[0];
        ulonglong2 a1 = ap[1];
        acc2[0] = ffma2(a0.x, ww, acc2[0]);
        acc2[1] = ffma2(a0.y, ww, acc2[1]);
        acc2[2] = ffma2(a1.x, ww, acc2[2]);
        acc2[3] = ffma2(a1.y, ww, acc2[3]);
    }
#pragma unroll
    for (int k = 0; k < 4; ++k) {
        float lo, hi;
        unpack2(acc2[k], lo, hi);
        s_red[h * 1152 + o * 9 + 2 * k + 0] = lo;
        s_red[h * 1152 + o * 9 + 2 * k + 1] = hi;
    }
    __syncthreads();

    const float bias = bmp[wm * EE + o];
#pragma unroll
    for (int p = 0; p < 2; ++p) {
        const int r = h + p * 4;          // rows 0..7
        const float v = s_red[0 * 1152 + o * 9 + r] +
                        s_red[1 * 1152 + o * 9 + r] +
                        s_red[2 * 1152 + o * 9 + r] +
                        s_red[3 * 1152 + o * 9 + r] + bias;
        g_agg1[((b0 + r) * MM + m) * EE + o] = v;
    }
}

// ---------------------------------------------------------------------------
// K3: fused QKV + attention + output projection (round-10 version, verbatim).
// grid = 128 blocks, 256 thr, 2 batches/block.  Dynamic smem = 96 KB.
// ---------------------------------------------------------------------------
__global__ __launch_bounds__(256) void k_mha(
    const float* __restrict__ Wq,         // [384,128]
    const float* __restrict__ bq,         // [384]
    const float* __restrict__ Wo,         // [128,128]
    const float* __restrict__ bo,         // [128]
    float* __restrict__ out)              // [M,B,E]
{
    extern __shared__ __align__(16) float smem[];
    float* s_ws  = smem;                  // 16384
    float* s_att = smem;                  // 1024 (union with s_ws)
    float* s_ao  = smem + 16384;          // 2048
    float* s_qkv = smem + 18432;          // 6144

    const int t  = threadIdx.x;
    const int g  = t >> 7;                // batch-local 0/1
    const int j  = t & 127;
    const int b0 = blockIdx.x * 2;

    // ---- Stage A: stage agg1 transposed: s_ao[g][e*8+m] ----
    for (int i = t; i < 2048; i += 256) {
        const int r = i >> 7;             // gg*8+m
        const int e = i & 127;
        const int gg = r >> 3, mm = r & 7;
        s_ao[gg * 1024 + e * 8 + mm] = g_agg1[((b0 + gg) * MM + mm) * EE + e];
    }

    // ---- Stage B: QKV, one full 128x128 weight chunk per jc ----
    for (int jc = 0; jc < 3; ++jc) {
        const int j0 = jc * 128;
        __syncthreads();                  // protect prev s_ws readers / s_ao
        for (int i = t; i < 16384; i += 256) {
            const int jj = i >> 7, ee = i & 127;
            s_ws[jj * 128 + (ee ^ (jj & 31))] = Wq[(j0 + jj) * EE + ee];
        }
        __syncthreads();

        unsigned long long acc2[4];
#pragma unroll
        for (int k = 0; k < 4; ++k) acc2[k] = 0ULL;
#pragma unroll 8
        for (int e = 0; e < 128; ++e) {
            const float w = s_ws[j * 128 + (e ^ (j & 31))];
            const unsigned long long ww = pack2(w, w);
            const ulonglong2* ap = (const ulonglong2*)&s_ao[g * 1024 + e * 8];
            ulonglong2 a0 = ap[0];
            ulonglong2 a1 = ap[1];
            acc2[0] = ffma2(a0.x, ww, acc2[0]);
            acc2[1] = ffma2(a0.y, ww, acc2[1]);
            acc2[2] = ffma2(a1.x, ww, acc2[2]);
            acc2[3] = ffma2(a1.y, ww, acc2[3]);
        }
        const float bias = bq[j0 + j];
#pragma unroll
        for (int k = 0; k < 4; ++k) {
            float lo, hi;
            unpack2(acc2[k], lo, hi);
            s_qkv[g * 3072 + (2 * k + 0) * JQKV + j0 + j] = lo + bias;
            s_qkv[g * 3072 + (2 * k + 1) * JQKV + j0 + j] = hi + bias;
        }
    }
    __syncthreads();                      // qkv complete; s_ws dead

    // ---- Stage C: attention ----
    if (t < 128) {
        const int gg = t >> 6;
        const int hm = t & 63;
        const int h  = hm >> 3;
        const int m  = hm & 7;
        const float* qp = &s_qkv[gg * 3072 + m * JQKV + h * HD];
        float sc[MM];
#pragma unroll
        for (int n = 0; n < MM; ++n) {
            const float* kp = &s_qkv[gg * 3072 + n * JQKV + EE + h * HD];
            float s = 0.0f;
#pragma unroll
            for (int d = 0; d < HD; ++d) s += qp[d] * kp[d];
            sc[n] = s * 0.25f;            // 1/sqrt(16)
        }
        float mx = sc[0];
#pragma unroll
        for (int n = 1; n < MM; ++n) mx = fmaxf(mx, sc[n]);
        float sum = 0.0f;
#pragma unroll
        for (int n = 0; n < MM; ++n) { sc[n] = __expf(sc[n] - mx); sum += sc[n]; }
        const float inv = 1.0f / sum;
#pragma unroll
        for (int n = 0; n < MM; ++n)
            s_att[(gg * 64 + hm) * 8 + n] = sc[n] * inv;
    }
    __syncthreads();

    {   // AV: o[g][e][m], e = j
        const int h = j >> 4;
        const float* vp = &s_qkv[g * 3072 + 2 * EE + j];
        float ov[MM];
#pragma unroll
        for (int m = 0; m < MM; ++m) {
            float v = 0.0f;
            const float* ap = &s_att[(g * 64 + h * 8 + m) * 8];
#pragma unroll
            for (int n = 0; n < MM; ++n) v += ap[n] * vp[n * JQKV];
            ov[m] = v;
        }
        __syncthreads();                  // done reading s_ao & s_att
#pragma unroll
        for (int m = 0; m < MM; ++m)
            s_ao[g * 1024 + j * 8 + m] = ov[m];
    }
    __syncthreads();                      // s_ao attn-out ready; s_att dead

    // ---- Stage D: output projection, single weight stage ----
    {
        for (int i = t; i < 16384; i += 256) {
            const int jj = i >> 7, ee = i & 127;
            s_ws[jj * 128 + (ee ^ (jj & 31))] = Wo[jj * EE + ee];
        }
        __syncthreads();

        unsigned long long acc2[4];
#pragma unroll
        for (int k = 0; k < 4; ++k) acc2[k] = 0ULL;
#pragma unroll 8
        for (int e = 0; e < 128; ++e) {
            const float w = s_ws[j * 128 + (e ^ (j & 31))];
            const unsigned long long ww = pack2(w, w);
            const ulonglong2* ap = (const ulonglong2*)&s_ao[g * 1024 + e * 8];
            ulonglong2 a0 = ap[0];
            ulonglong2 a1 = ap[1];
            acc2[0] = ffma2(a0.x, ww, acc2[0]);
            acc2[1] = ffma2(a0.y, ww, acc2[1]);
            acc2[2] = ffma2(a1.x, ww, acc2[2]);
            acc2[3] = ffma2(a1.y, ww, acc2[3]);
        }
        const float bias = bo[j];
        const int b = b0 + g;
#pragma unroll
        for (int k = 0; k < 4; ++k) {
            float lo, hi;
            unpack2(acc2[k], lo, hi);
            out[((2 * k + 0) * BB + b) * EE + j] = lo + bias;
            out[((2 * k + 1) * BB + b) * EE + j] = hi + bias;
        }
    }
}

// ---------------------------------------------------------------------------
extern "C" void kernel_launch(void* const* d_in, const int* in_sizes, int n_in,
                              void* d_out, int out_size) {
    const int*   mp_type = (const int*)d_in[1];
    const int*   walks   = (const int*)d_in[2];
    const float* nt      = (const float*)d_in[3];
    const float* fb      = (const float*)d_in[4];
    const float* et      = (const float*)d_in[5];
    const float* W_mp    = (const float*)d_in[6];
    const float* b_mp    = (const float*)d_in[7];
    const float* Wqkv    = (const float*)d_in[8];
    const float* bqkv    = (const float*)d_in[9];
    const float* Wo      = (const float*)d_in[10];
    const float* bo      = (const float*)d_in[11];
    float* out = (float*)d_out;

    static const size_t MHA_SMEM = 24576 * sizeof(float);   // 96 KB
    cudaFuncSetAttribute(k_mha, cudaFuncAttributeMaxDynamicSharedMemorySize,
                         (int)MHA_SMEM);

    k_gather<<<BB * MM, 128>>>(walks, nt, fb, et);
    k_mp<<<dim3(BB / 8, MM), 512>>>(mp_type, W_mp, b_mp);
    k_mha<<<BB / 2, 256, MHA_SMEM>>>(Wqkv, bqkv, Wo, bo, out);
}